// round 5
// baseline (speedup 1.0000x reference)
#include <cuda_runtime.h>
#include <cuda_bf16.h>
#include <stdint.h>
#include <math.h>

#define BN 4
#define CN 64
#define HN 128
#define WN 128
#define SN (HN*WN)      // 16384
#define NP (BN*SN)      // 65536

// Scratch (device globals; no allocations allowed)
__device__ float g_y1[NP*CN];   // layer-1 output, NCHW
__device__ float g_rfh[NP];     // rf_h / 2
__device__ float g_rfw[NP];     // rf_w / 2

// ---------------- smem layout (dynamic) ----------------
// B tiles: [9 taps][64 o rows x 64 c cols] bf16, SW128-swizzled, 8KB/tap
#define B_HI_OFF 0
#define B_LO_OFF 73728
// A tiles: [2 buf][128 px rows x 64 c cols] bf16, SW128-swizzled, 16KB each
#define A_HI_OFF 147456
#define A_LO_OFF 180224
#define BIAS_OFF 212992
#define SMEM_TOTAL 213248

__device__ __forceinline__ uint32_t swz(uint32_t off) { return off ^ ((off >> 3) & 0x70); }
__device__ __forceinline__ uint32_t pk2(float a, float b) {
    __nv_bfloat162 t = __floats2bfloat162_rn(a, b);
    return *(uint32_t*)&t;
}

__device__ __forceinline__ void mma_bf16(float& d0, float& d1, float& d2, float& d3,
                                         uint32_t a0, uint32_t a1, uint32_t a2, uint32_t a3,
                                         uint32_t b0, uint32_t b1)
{
    asm volatile("mma.sync.aligned.m16n8k16.row.col.f32.bf16.bf16.f32 "
                 "{%0,%1,%2,%3}, {%4,%5,%6,%7}, {%8,%9}, {%0,%1,%2,%3};"
                 : "+f"(d0), "+f"(d1), "+f"(d2), "+f"(d3)
                 : "r"(a0), "r"(a1), "r"(a2), "r"(a3), "r"(b0), "r"(b1));
}

// ---------------------------------------------------------------------------
// Offset conv (NCHW) — unchanged (known good).
// ---------------------------------------------------------------------------
__global__ __launch_bounds__(256)
void offset_conv(const float* __restrict__ xin,
                 const float* __restrict__ woff,
                 const float* __restrict__ boff,
                 const int* __restrict__ p_lo, const int* __restrict__ p_hi,
                 float* __restrict__ rfh, float* __restrict__ rfw)
{
    __shared__ float sw[CN * 18];
    for (int d = threadIdx.x; d < CN * 18; d += 256) {
        int c = d / 18;
        int k = (d % 18) >> 1;
        int j = d & 1;
        sw[d] = woff[(j * CN + c) * 9 + k];
    }
    __syncthreads();

    int p  = blockIdx.x * 256 + threadIdx.x;
    int b  = p >> 14;
    int hw = p & (SN - 1);
    int h  = hw >> 7;
    int w  = hw & (WN - 1);

    bool hm = h > 0, hp = h < HN - 1, wm = w > 0, wp = w < WN - 1;

    float a0 = boff[0], a1 = boff[1];
    const float* xb = xin + (size_t)b * CN * SN;

    #pragma unroll 2
    for (int c = 0; c < CN; c++) {
        const float* xc = xb + c * SN + hw;
        float v[9];
        v[4] = xc[0];
        v[1] = hm ? xc[-WN] : 0.f;
        v[7] = hp ? xc[ WN] : 0.f;
        v[3] = wm ? xc[-1] : 0.f;
        v[5] = wp ? xc[ 1] : 0.f;
        v[0] = (hm && wm) ? xc[-WN - 1] : 0.f;
        v[2] = (hm && wp) ? xc[-WN + 1] : 0.f;
        v[6] = (hp && wm) ? xc[ WN - 1] : 0.f;
        v[8] = (hp && wp) ? xc[ WN + 1] : 0.f;
        const float* wc = sw + c * 18;
        #pragma unroll
        for (int k = 0; k < 9; k++) {
            a0 += v[k] * wc[k * 2 + 0];
            a1 += v[k] * wc[k * 2 + 1];
        }
    }

    float lo   = (float)(*p_lo);
    float span = (float)(*p_hi) - lo;
    float s0 = 1.f / (1.f + __expf(-a0));
    float s1 = 1.f / (1.f + __expf(-a1));
    rfh[p] = 0.5f * (lo + span * s0);
    rfw[p] = 0.5f * (lo + span * s1);
}

// ---------------------------------------------------------------------------
// Pipelined mma.sync ARConv: double-buffered A, per-quarter interleave of
// next-tap gather LDGs with current-tap MMA consume. 1 syncthreads per tap.
// ---------------------------------------------------------------------------
__global__ __launch_bounds__(256, 1)
void arconv_mma(const float* __restrict__ xin,
                const float* __restrict__ rfh, const float* __restrict__ rfw,
                const float* __restrict__ Wk,      // [O][C][3][3]
                const float* __restrict__ bias,    // [O]
                const float* __restrict__ resid,   // NCHW (mode 1) or null
                float* __restrict__ outp,
                int mode)
{
    extern __shared__ char smem[];
    int tid = threadIdx.x, wid = tid >> 5, lid = tid & 31;
    int g = lid >> 2, t = lid & 3;   // mma quad coords

    // B hi/lo conversion into SW128-swizzled tap tiles [o rows x c cols]
    for (int d = tid; d < 9 * 64 * 64; d += 256) {
        int tap = d >> 12;
        int o   = (d >> 6) & 63;
        int c   = d & 63;
        float wv = Wk[(o * 64 + c) * 9 + tap];
        __nv_bfloat16 hb = __float2bfloat16(wv);
        float hf = __bfloat162float(hb);
        __nv_bfloat16 lb = __float2bfloat16(wv - hf);
        uint32_t s = tap * 8192 + swz((uint32_t)(o * 128 + c * 2));
        *(__nv_bfloat16*)(smem + B_HI_OFF + s) = hb;
        *(__nv_bfloat16*)(smem + B_LO_OFF + s) = lb;
    }
    if (tid < 64) *(float*)(smem + BIAS_OFF + tid * 4) = bias[tid];
    __syncthreads();

    const float* biasS = (const float*)(smem + BIAS_OFF);

    for (int it = 0; it < 4; it++) {
        int tile = blockIdx.x * 4 + it;
        int p0 = tile * 128;

        // ---- per-pixel sampling geometry (producer role) ----
        int px = tid & 127;
        int cbase = (tid >> 7) * 32;
        int p = p0 + px;
        int b = p >> 14;
        int hw = p & (SN - 1);
        int h = hw >> 7;
        int w = hw & (WN - 1);

        float rh = rfh[p];
        float rw = rfw[p];

        float xsl = (float)w - rw, xsr = (float)w + rw;
        float xl0f = floorf(xsl), xr0f = floorf(xsr);
        float txl = xsl - xl0f, txr = xsr - xr0f;
        int xl0 = min(max((int)xl0f, 0), WN - 1); int xl1 = min(xl0 + 1, WN - 1);
        int xr0 = min(max((int)xr0f, 0), WN - 1); int xr1 = min(xr0 + 1, WN - 1);

        float ysa = (float)h - rh, ysb = (float)h + rh;
        float ya0f = floorf(ysa), yb0f = floorf(ysb);
        float tya = ysa - ya0f, tyb = ysb - yb0f;
        int ya0 = min(max((int)ya0f, 0), HN - 1); int ya1 = min(ya0 + 1, HN - 1);
        int yb0 = min(max((int)yb0f, 0), HN - 1); int yb1 = min(yb0 + 1, HN - 1);

        int oa0 = ya0 * WN, oa1 = ya1 * WN, ohh = h * WN, ob0 = yb0 * WN, ob1 = yb1 * WN;

        const float* xb = xin + (size_t)(b * CN + cbase) * SN;
        uint32_t sbase = (uint32_t)(px * 128 + cbase * 2);

        float acc[8][4];
        #pragma unroll
        for (int nb = 0; nb < 8; nb++)
            #pragma unroll
            for (int j = 0; j < 4; j++) acc[nb][j] = 0.f;

        // ---- prologue: produce tap 0 (corner: oa0/oa1, xl0/xl1) into buf 0 ----
        #pragma unroll
        for (int q = 0; q < 4; q++) {
            const float* xc = xb + (size_t)(q * 8) * SN;
            float ra[8], rb[8], rc[8], rd[8], v[8];
            #pragma unroll
            for (int j = 0; j < 8; j++) {
                ra[j] = xc[(size_t)j * SN + oa0 + xl0];
                rb[j] = xc[(size_t)j * SN + oa0 + xl1];
                rc[j] = xc[(size_t)j * SN + oa1 + xl0];
                rd[j] = xc[(size_t)j * SN + oa1 + xl1];
            }
            #pragma unroll
            for (int j = 0; j < 8; j++) {
                float t0 = fmaf(txl, rb[j] - ra[j], ra[j]);
                float t1 = fmaf(txl, rd[j] - rc[j], rc[j]);
                v[j] = fmaf(tya, t1 - t0, t0);
            }
            float hf[8], lo[8];
            #pragma unroll
            for (int j = 0; j < 8; j++) {
                __nv_bfloat16 hb = __float2bfloat16(v[j]);
                hf[j] = __bfloat162float(hb);
                lo[j] = v[j] - hf[j];
            }
            uint4 HV, LV;
            HV.x = pk2(hf[0], hf[1]); HV.y = pk2(hf[2], hf[3]);
            HV.z = pk2(hf[4], hf[5]); HV.w = pk2(hf[6], hf[7]);
            LV.x = pk2(lo[0], lo[1]); LV.y = pk2(lo[2], lo[3]);
            LV.z = pk2(lo[4], lo[5]); LV.w = pk2(lo[6], lo[7]);
            uint32_t s = swz(sbase + q * 16);
            *(uint4*)(smem + A_HI_OFF + s) = HV;
            *(uint4*)(smem + A_LO_OFF + s) = LV;
        }
        __syncthreads();

        // ---- main tap loop ----
        #pragma unroll 1
        for (int tap = 0; tap < 9; tap++) {
            int buf = tap & 1;
            bool have = tap < 8;
            int nt = tap + 1;
            int nky = (nt >= 6) ? 2 : (nt >= 3) ? 1 : 0;
            int nkx = nt - nky * 3;
            int nry0 = (nky == 0) ? oa0 : (nky == 1) ? ohh : ob0;
            int nry1 = (nky == 0) ? oa1 : (nky == 1) ? ohh : ob1;
            float nty = (nky == 0) ? tya : (nky == 1) ? 0.f : tyb;
            int nx0 = (nkx == 0) ? xl0 : (nkx == 1) ? w : xr0;
            int nx1 = (nkx == 0) ? xl1 : (nkx == 1) ? w : xr1;
            float ntx = (nkx == 0) ? txl : (nkx == 1) ? 0.f : txr;
            bool ncy = (nky == 1), ncx = (nkx == 1);

            char* Ah = smem + A_HI_OFF + (buf ^ 1) * 16384;
            char* Al = smem + A_LO_OFF + (buf ^ 1) * 16384;
            const char* Ch = smem + A_HI_OFF + buf * 16384;
            const char* Cl = smem + A_LO_OFF + buf * 16384;
            uint32_t btap = tap * 8192;
            int rbase = 16 * wid;

            #pragma unroll
            for (int q = 0; q < 4; q++) {
                // -- (1) issue gather loads for next tap, quarter q --
                float ra[8], rb[8], rc[8], rd[8];
                const float* xc = xb + (size_t)(q * 8) * SN;
                if (have) {
                    if (ncy && ncx) {
                        #pragma unroll
                        for (int j = 0; j < 8; j++) ra[j] = xc[(size_t)j * SN + ohh + w];
                    } else if (ncy) {
                        #pragma unroll
                        for (int j = 0; j < 8; j++) {
                            ra[j] = xc[(size_t)j * SN + ohh + nx0];
                            rb[j] = xc[(size_t)j * SN + ohh + nx1];
                        }
                    } else if (ncx) {
                        #pragma unroll
                        for (int j = 0; j < 8; j++) {
                            ra[j] = xc[(size_t)j * SN + nry0 + w];
                            rb[j] = xc[(size_t)j * SN + nry1 + w];
                        }
                    } else {
                        #pragma unroll
                        for (int j = 0; j < 8; j++) {
                            ra[j] = xc[(size_t)j * SN + nry0 + nx0];
                            rb[j] = xc[(size_t)j * SN + nry0 + nx1];
                            rc[j] = xc[(size_t)j * SN + nry1 + nx0];
                            rd[j] = xc[(size_t)j * SN + nry1 + nx1];
                        }
                    }
                }

                // -- (2) consume chunk q of current tap (MMA) --
                {
                    int ck = q * 16;
                    uint32_t ar0 = swz((uint32_t)((rbase + g) * 128 + (ck + 2 * t) * 2));
                    uint32_t ar1 = swz((uint32_t)((rbase + g + 8) * 128 + (ck + 2 * t) * 2));
                    uint32_t ac0 = swz((uint32_t)((rbase + g) * 128 + (ck + 2 * t + 8) * 2));
                    uint32_t ac1 = swz((uint32_t)((rbase + g + 8) * 128 + (ck + 2 * t + 8) * 2));
                    uint32_t ah0 = *(const uint32_t*)(Ch + ar0);
                    uint32_t ah1 = *(const uint32_t*)(Ch + ar1);
                    uint32_t ah2 = *(const uint32_t*)(Ch + ac0);
                    uint32_t ah3 = *(const uint32_t*)(Ch + ac1);
                    uint32_t al0 = *(const uint32_t*)(Cl + ar0);
                    uint32_t al1 = *(const uint32_t*)(Cl + ar1);
                    uint32_t al2 = *(const uint32_t*)(Cl + ac0);
                    uint32_t al3 = *(const uint32_t*)(Cl + ac1);

                    #pragma unroll
                    for (int nb = 0; nb < 8; nb++) {
                        int o = nb * 8 + g;
                        uint32_t br0 = swz((uint32_t)(o * 128 + (ck + 2 * t) * 2));
                        uint32_t br1 = swz((uint32_t)(o * 128 + (ck + 2 * t + 8) * 2));
                        uint32_t bh0 = *(const uint32_t*)(smem + B_HI_OFF + btap + br0);
                        uint32_t bh1 = *(const uint32_t*)(smem + B_HI_OFF + btap + br1);
                        uint32_t bl0 = *(const uint32_t*)(smem + B_LO_OFF + btap + br0);
                        uint32_t bl1 = *(const uint32_t*)(smem + B_LO_OFF + btap + br1);

                        mma_bf16(acc[nb][0], acc[nb][1], acc[nb][2], acc[nb][3],
                                 ah0, ah1, ah2, ah3, bh0, bh1);
                        mma_bf16(acc[nb][0], acc[nb][1], acc[nb][2], acc[nb][3],
                                 al0, al1, al2, al3, bh0, bh1);
                        mma_bf16(acc[nb][0], acc[nb][1], acc[nb][2], acc[nb][3],
                                 ah0, ah1, ah2, ah3, bl0, bl1);
                    }
                }

                // -- (3) finish next-tap quarter: lerp, convert, STS --
                if (have) {
                    float v[8];
                    if (ncy && ncx) {
                        #pragma unroll
                        for (int j = 0; j < 8; j++) v[j] = ra[j];
                    } else if (ncy) {
                        #pragma unroll
                        for (int j = 0; j < 8; j++) v[j] = fmaf(ntx, rb[j] - ra[j], ra[j]);
                    } else if (ncx) {
                        #pragma unroll
                        for (int j = 0; j < 8; j++) v[j] = fmaf(nty, rb[j] - ra[j], ra[j]);
                    } else {
                        #pragma unroll
                        for (int j = 0; j < 8; j++) {
                            float t0 = fmaf(ntx, rb[j] - ra[j], ra[j]);
                            float t1 = fmaf(ntx, rd[j] - rc[j], rc[j]);
                            v[j] = fmaf(nty, t1 - t0, t0);
                        }
                    }
                    float hf[8], lo[8];
                    #pragma unroll
                    for (int j = 0; j < 8; j++) {
                        __nv_bfloat16 hb = __float2bfloat16(v[j]);
                        hf[j] = __bfloat162float(hb);
                        lo[j] = v[j] - hf[j];
                    }
                    uint4 HV, LV;
                    HV.x = pk2(hf[0], hf[1]); HV.y = pk2(hf[2], hf[3]);
                    HV.z = pk2(hf[4], hf[5]); HV.w = pk2(hf[6], hf[7]);
                    LV.x = pk2(lo[0], lo[1]); LV.y = pk2(lo[2], lo[3]);
                    LV.z = pk2(lo[4], lo[5]); LV.w = pk2(lo[6], lo[7]);
                    uint32_t s = swz(sbase + q * 16);
                    *(uint4*)(Ah + s) = HV;
                    *(uint4*)(Al + s) = LV;
                }
            }
            __syncthreads();
        }

        // ---- epilogue: D fragment -> NCHW ----
        {
            int px0 = p0 + 16 * wid + g;
            int px1 = px0 + 8;
            int b0i = px0 >> 14, hw0 = px0 & (SN - 1);
            int b1i = px1 >> 14, hw1 = px1 & (SN - 1);
            #pragma unroll
            for (int nb = 0; nb < 8; nb++) {
                int o0 = nb * 8 + 2 * t;
                int o1 = o0 + 1;
                size_t i00 = ((size_t)(b0i * CN + o0)) * SN + hw0;
                size_t i01 = ((size_t)(b0i * CN + o1)) * SN + hw0;
                size_t i10 = ((size_t)(b1i * CN + o0)) * SN + hw1;
                size_t i11 = ((size_t)(b1i * CN + o1)) * SN + hw1;
                float v00 = acc[nb][0] + biasS[o0];
                float v01 = acc[nb][1] + biasS[o1];
                float v10 = acc[nb][2] + biasS[o0];
                float v11 = acc[nb][3] + biasS[o1];
                if (mode == 0) {
                    outp[i00] = fmaxf(v00, 0.f);
                    outp[i01] = fmaxf(v01, 0.f);
                    outp[i10] = fmaxf(v10, 0.f);
                    outp[i11] = fmaxf(v11, 0.f);
                } else {
                    outp[i00] = v00 + resid[i00];
                    outp[i01] = v01 + resid[i01];
                    outp[i10] = v10 + resid[i10];
                    outp[i11] = v11 + resid[i11];
                }
            }
        }
        __syncthreads();
    }
}

// ---------------------------------------------------------------------------
extern "C" void kernel_launch(void* const* d_in, const int* in_sizes, int n_in,
                              void* d_out, int out_size)
{
    const float* x     = (const float*)d_in[0];
    const float* woff1 = (const float*)d_in[1];
    const float* boff1 = (const float*)d_in[2];
    const float* W1    = (const float*)d_in[3];
    const float* b1    = (const float*)d_in[4];
    const float* woff2 = (const float*)d_in[5];
    const float* boff2 = (const float*)d_in[6];
    const float* W2    = (const float*)d_in[7];
    const float* b2    = (const float*)d_in[8];
    const int*   lo    = (const int*)d_in[10];
    const int*   hi    = (const int*)d_in[11];
    float* out = (float*)d_out;

    float *y1, *rfh, *rfw;
    cudaGetSymbolAddress((void**)&y1,  g_y1);
    cudaGetSymbolAddress((void**)&rfh, g_rfh);
    cudaGetSymbolAddress((void**)&rfw, g_rfw);

    cudaFuncSetAttribute(arconv_mma, cudaFuncAttributeMaxDynamicSharedMemorySize, SMEM_TOTAL);

    // Layer 1
    offset_conv<<<NP / 256, 256>>>(x, woff1, boff1, lo, hi, rfh, rfw);
    arconv_mma<<<128, 256, SMEM_TOTAL>>>(x, rfh, rfw, W1, b1, nullptr, y1, 0);

    // Layer 2 (+ residual)
    offset_conv<<<NP / 256, 256>>>(y1, woff2, boff2, lo, hi, rfh, rfw);
    arconv_mma<<<128, 256, SMEM_TOTAL>>>(y1, rfh, rfw, W2, b2, x, out, 1);
}

// round 6
// speedup vs baseline: 1.0562x; 1.0562x over previous
#include <cuda_runtime.h>
#include <cuda_bf16.h>
#include <stdint.h>
#include <math.h>

#define BN 4
#define CN 64
#define HN 128
#define WN 128
#define SN (HN*WN)      // 16384
#define NP (BN*SN)      // 65536

// Scratch (device globals; no allocations allowed)
__device__ float g_y1[NP*CN];   // layer-1 output, NCHW
__device__ float g_rfh[NP];     // rf_h / 2
__device__ float g_rfw[NP];     // rf_w / 2

// ---------------- smem layout (dynamic) ----------------
// B tiles: [9 taps][64 o rows x 64 c cols] bf16, SW128-swizzled, 8KB/tap
#define B_HI_OFF 0
#define B_LO_OFF 73728
// A tile:  [128 px rows x 64 c cols] bf16, SW128-swizzled, 16KB each of hi/lo
#define A_HI_OFF 147456
#define A_LO_OFF 163840
#define BIAS_OFF 180224
#define SMEM_TOTAL 180480

__device__ __forceinline__ uint32_t swz(uint32_t off) { return off ^ ((off >> 3) & 0x70); }
__device__ __forceinline__ uint32_t pk2(float a, float b) {
    __nv_bfloat162 t = __floats2bfloat162_rn(a, b);
    return *(uint32_t*)&t;
}

__device__ __forceinline__ void mma_bf16(float& d0, float& d1, float& d2, float& d3,
                                         uint32_t a0, uint32_t a1, uint32_t a2, uint32_t a3,
                                         uint32_t b0, uint32_t b1)
{
    asm volatile("mma.sync.aligned.m16n8k16.row.col.f32.bf16.bf16.f32 "
                 "{%0,%1,%2,%3}, {%4,%5,%6,%7}, {%8,%9}, {%0,%1,%2,%3};"
                 : "+f"(d0), "+f"(d1), "+f"(d2), "+f"(d3)
                 : "r"(a0), "r"(a1), "r"(a2), "r"(a3), "r"(b0), "r"(b1));
}

// ---------------------------------------------------------------------------
// Offset conv (NCHW) — unchanged (known good).
// ---------------------------------------------------------------------------
__global__ __launch_bounds__(256)
void offset_conv(const float* __restrict__ xin,
                 const float* __restrict__ woff,
                 const float* __restrict__ boff,
                 const int* __restrict__ p_lo, const int* __restrict__ p_hi,
                 float* __restrict__ rfh, float* __restrict__ rfw)
{
    __shared__ float sw[CN * 18];
    for (int d = threadIdx.x; d < CN * 18; d += 256) {
        int c = d / 18;
        int k = (d % 18) >> 1;
        int j = d & 1;
        sw[d] = woff[(j * CN + c) * 9 + k];
    }
    __syncthreads();

    int p  = blockIdx.x * 256 + threadIdx.x;
    int b  = p >> 14;
    int hw = p & (SN - 1);
    int h  = hw >> 7;
    int w  = hw & (WN - 1);

    bool hm = h > 0, hp = h < HN - 1, wm = w > 0, wp = w < WN - 1;

    float a0 = boff[0], a1 = boff[1];
    const float* xb = xin + (size_t)b * CN * SN;

    #pragma unroll 2
    for (int c = 0; c < CN; c++) {
        const float* xc = xb + c * SN + hw;
        float v[9];
        v[4] = xc[0];
        v[1] = hm ? xc[-WN] : 0.f;
        v[7] = hp ? xc[ WN] : 0.f;
        v[3] = wm ? xc[-1] : 0.f;
        v[5] = wp ? xc[ 1] : 0.f;
        v[0] = (hm && wm) ? xc[-WN - 1] : 0.f;
        v[2] = (hm && wp) ? xc[-WN + 1] : 0.f;
        v[6] = (hp && wm) ? xc[ WN - 1] : 0.f;
        v[8] = (hp && wp) ? xc[ WN + 1] : 0.f;
        const float* wc = sw + c * 18;
        #pragma unroll
        for (int k = 0; k < 9; k++) {
            a0 += v[k] * wc[k * 2 + 0];
            a1 += v[k] * wc[k * 2 + 1];
        }
    }

    float lo   = (float)(*p_lo);
    float span = (float)(*p_hi) - lo;
    float s0 = 1.f / (1.f + __expf(-a0));
    float s1 = 1.f / (1.f + __expf(-a1));
    rfh[p] = 0.5f * (lo + span * s0);
    rfw[p] = 0.5f * (lo + span * s1);
}

// ---------------------------------------------------------------------------
// mma.sync ARConv, 512 threads / 16 warps. Warp w: px rows [16*(w&7), +16),
// o range [32*(w>>3), +32). Producers: 4 threads/px x 16 channels.
// Serial produce -> consume per tap (no reg-pressure pipeline).
// ---------------------------------------------------------------------------
__global__ __launch_bounds__(512, 1)
void arconv_mma(const float* __restrict__ xin,
                const float* __restrict__ rfh, const float* __restrict__ rfw,
                const float* __restrict__ Wk,      // [O][C][3][3]
                const float* __restrict__ bias,    // [O]
                const float* __restrict__ resid,   // NCHW (mode 1) or null
                float* __restrict__ outp,
                int mode)
{
    extern __shared__ char smem[];
    int tid = threadIdx.x, wid = tid >> 5, lid = tid & 31;
    int g = lid >> 2, t = lid & 3;   // mma quad coords
    int ohalf = wid >> 3;            // 0 or 1: which 32-o half this warp computes
    int rbase = 16 * (wid & 7);      // px row base for this warp

    // B hi/lo conversion into SW128-swizzled tap tiles [o rows x c cols]
    for (int d = tid; d < 9 * 64 * 64; d += 512) {
        int tap = d >> 12;
        int o   = (d >> 6) & 63;
        int c   = d & 63;
        float wv = Wk[(o * 64 + c) * 9 + tap];
        __nv_bfloat16 hb = __float2bfloat16(wv);
        float hf = __bfloat162float(hb);
        __nv_bfloat16 lb = __float2bfloat16(wv - hf);
        uint32_t s = tap * 8192 + swz((uint32_t)(o * 128 + c * 2));
        *(__nv_bfloat16*)(smem + B_HI_OFF + s) = hb;
        *(__nv_bfloat16*)(smem + B_LO_OFF + s) = lb;
    }
    if (tid < 64) *(float*)(smem + BIAS_OFF + tid * 4) = bias[tid];
    __syncthreads();

    const float* biasS = (const float*)(smem + BIAS_OFF);

    for (int it = 0; it < 4; it++) {
        int tile = blockIdx.x * 4 + it;
        int p0 = tile * 128;

        // ---- per-pixel sampling geometry (producer role) ----
        int px = tid & 127;
        int cbase = (tid >> 7) * 16;     // 4 producer groups of 16 channels
        int p = p0 + px;
        int b = p >> 14;
        int hw = p & (SN - 1);
        int h = hw >> 7;
        int w = hw & (WN - 1);

        float rh = rfh[p];
        float rw = rfw[p];

        float xsl = (float)w - rw, xsr = (float)w + rw;
        float xl0f = floorf(xsl), xr0f = floorf(xsr);
        float txl = xsl - xl0f, txr = xsr - xr0f;
        int xl0 = min(max((int)xl0f, 0), WN - 1); int xl1 = min(xl0 + 1, WN - 1);
        int xr0 = min(max((int)xr0f, 0), WN - 1); int xr1 = min(xr0 + 1, WN - 1);

        float ysa = (float)h - rh, ysb = (float)h + rh;
        float ya0f = floorf(ysa), yb0f = floorf(ysb);
        float tya = ysa - ya0f, tyb = ysb - yb0f;
        int ya0 = min(max((int)ya0f, 0), HN - 1); int ya1 = min(ya0 + 1, HN - 1);
        int yb0 = min(max((int)yb0f, 0), HN - 1); int yb1 = min(yb0 + 1, HN - 1);

        int oa0 = ya0 * WN, oa1 = ya1 * WN, ohh = h * WN, ob0 = yb0 * WN, ob1 = yb1 * WN;

        const float* xb = xin + (size_t)(b * CN + cbase) * SN;
        uint32_t sbase = (uint32_t)(px * 128 + cbase * 2);

        // mma accumulators: [nb 0..3][c0..c3]  (32 o per warp)
        float acc[4][4];
        #pragma unroll
        for (int nb = 0; nb < 4; nb++)
            #pragma unroll
            for (int j = 0; j < 4; j++) acc[nb][j] = 0.f;

        #pragma unroll 1
        for (int tap = 0; tap < 9; tap++) {
            int ky = (tap >= 6) ? 2 : (tap >= 3) ? 1 : 0;
            int kx = tap - ky * 3;

            int ry0 = (ky == 0) ? oa0 : (ky == 1) ? ohh : ob0;
            int ry1 = (ky == 0) ? oa1 : (ky == 1) ? ohh : ob1;
            float tyv = (ky == 0) ? tya : (ky == 1) ? 0.f : tyb;
            int x0 = (kx == 0) ? xl0 : (kx == 1) ? w : xr0;
            int x1 = (kx == 0) ? xl1 : (kx == 1) ? w : xr1;
            float txv = (kx == 0) ? txl : (kx == 1) ? 0.f : txr;
            bool cy = (ky == 1), cx = (kx == 1);

            // ---- produce A tile for this tap (16 channels per thread) ----
            #pragma unroll 1
            for (int cg = 0; cg < 2; cg++) {
                const float* xc = xb + (size_t)(cg * 8) * SN;
                float v[8];
                if (cy && cx) {
                    #pragma unroll
                    for (int j = 0; j < 8; j++) v[j] = xc[(size_t)j * SN + ohh + w];
                } else if (cy) {
                    float q0[8], q1[8];
                    #pragma unroll
                    for (int j = 0; j < 8; j++) {
                        q0[j] = xc[(size_t)j * SN + ohh + x0];
                        q1[j] = xc[(size_t)j * SN + ohh + x1];
                    }
                    #pragma unroll
                    for (int j = 0; j < 8; j++) v[j] = fmaf(txv, q1[j] - q0[j], q0[j]);
                } else if (cx) {
                    float q0[8], q1[8];
                    #pragma unroll
                    for (int j = 0; j < 8; j++) {
                        q0[j] = xc[(size_t)j * SN + ry0 + w];
                        q1[j] = xc[(size_t)j * SN + ry1 + w];
                    }
                    #pragma unroll
                    for (int j = 0; j < 8; j++) v[j] = fmaf(tyv, q1[j] - q0[j], q0[j]);
                } else {
                    float a0[8], a1[8], c0[8], c1[8];
                    #pragma unroll
                    for (int j = 0; j < 8; j++) {
                        a0[j] = xc[(size_t)j * SN + ry0 + x0];
                        a1[j] = xc[(size_t)j * SN + ry0 + x1];
                        c0[j] = xc[(size_t)j * SN + ry1 + x0];
                        c1[j] = xc[(size_t)j * SN + ry1 + x1];
                    }
                    #pragma unroll
                    for (int j = 0; j < 8; j++) {
                        float t0 = fmaf(txv, a1[j] - a0[j], a0[j]);
                        float t1 = fmaf(txv, c1[j] - c0[j], c0[j]);
                        v[j] = fmaf(tyv, t1 - t0, t0);
                    }
                }

                float hf[8], lo[8];
                #pragma unroll
                for (int j = 0; j < 8; j++) {
                    __nv_bfloat16 hb = __float2bfloat16(v[j]);
                    hf[j] = __bfloat162float(hb);
                    lo[j] = v[j] - hf[j];
                }
                uint4 HV, LV;
                HV.x = pk2(hf[0], hf[1]); HV.y = pk2(hf[2], hf[3]);
                HV.z = pk2(hf[4], hf[5]); HV.w = pk2(hf[6], hf[7]);
                LV.x = pk2(lo[0], lo[1]); LV.y = pk2(lo[2], lo[3]);
                LV.z = pk2(lo[4], lo[5]); LV.w = pk2(lo[6], lo[7]);

                uint32_t s = swz(sbase + cg * 16);
                *(uint4*)(smem + A_HI_OFF + s) = HV;
                *(uint4*)(smem + A_LO_OFF + s) = LV;
            }

            __syncthreads();

            // ---- consume: warp computes 16 px x 32 o ----
            {
                uint32_t btap = tap * 8192;
                #pragma unroll
                for (int chunk = 0; chunk < 4; chunk++) {
                    int ck = chunk * 16;
                    uint32_t ar0 = swz((uint32_t)((rbase + g) * 128 + (ck + 2 * t) * 2));
                    uint32_t ar1 = swz((uint32_t)((rbase + g + 8) * 128 + (ck + 2 * t) * 2));
                    uint32_t ac0 = swz((uint32_t)((rbase + g) * 128 + (ck + 2 * t + 8) * 2));
                    uint32_t ac1 = swz((uint32_t)((rbase + g + 8) * 128 + (ck + 2 * t + 8) * 2));
                    uint32_t ah0 = *(const uint32_t*)(smem + A_HI_OFF + ar0);
                    uint32_t ah1 = *(const uint32_t*)(smem + A_HI_OFF + ar1);
                    uint32_t ah2 = *(const uint32_t*)(smem + A_HI_OFF + ac0);
                    uint32_t ah3 = *(const uint32_t*)(smem + A_HI_OFF + ac1);
                    uint32_t al0 = *(const uint32_t*)(smem + A_LO_OFF + ar0);
                    uint32_t al1 = *(const uint32_t*)(smem + A_LO_OFF + ar1);
                    uint32_t al2 = *(const uint32_t*)(smem + A_LO_OFF + ac0);
                    uint32_t al3 = *(const uint32_t*)(smem + A_LO_OFF + ac1);

                    #pragma unroll
                    for (int nb = 0; nb < 4; nb++) {
                        int o = ohalf * 32 + nb * 8 + g;
                        uint32_t br0 = swz((uint32_t)(o * 128 + (ck + 2 * t) * 2));
                        uint32_t br1 = swz((uint32_t)(o * 128 + (ck + 2 * t + 8) * 2));
                        uint32_t bh0 = *(const uint32_t*)(smem + B_HI_OFF + btap + br0);
                        uint32_t bh1 = *(const uint32_t*)(smem + B_HI_OFF + btap + br1);
                        uint32_t bl0 = *(const uint32_t*)(smem + B_LO_OFF + btap + br0);
                        uint32_t bl1 = *(const uint32_t*)(smem + B_LO_OFF + btap + br1);

                        mma_bf16(acc[nb][0], acc[nb][1], acc[nb][2], acc[nb][3],
                                 ah0, ah1, ah2, ah3, bh0, bh1);
                        mma_bf16(acc[nb][0], acc[nb][1], acc[nb][2], acc[nb][3],
                                 al0, al1, al2, al3, bh0, bh1);
                        mma_bf16(acc[nb][0], acc[nb][1], acc[nb][2], acc[nb][3],
                                 ah0, ah1, ah2, ah3, bl0, bl1);
                    }
                }
            }
            __syncthreads();   // protect A before next tap's produce
        }

        // ---- epilogue: D fragment -> NCHW ----
        {
            int px0 = p0 + rbase + g;
            int px1 = px0 + 8;
            int b0i = px0 >> 14, hw0 = px0 & (SN - 1);
            int b1i = px1 >> 14, hw1 = px1 & (SN - 1);
            #pragma unroll
            for (int nb = 0; nb < 4; nb++) {
                int o0 = ohalf * 32 + nb * 8 + 2 * t;
                int o1 = o0 + 1;
                size_t i00 = ((size_t)(b0i * CN + o0)) * SN + hw0;
                size_t i01 = ((size_t)(b0i * CN + o1)) * SN + hw0;
                size_t i10 = ((size_t)(b1i * CN + o0)) * SN + hw1;
                size_t i11 = ((size_t)(b1i * CN + o1)) * SN + hw1;
                float v00 = acc[nb][0] + biasS[o0];
                float v01 = acc[nb][1] + biasS[o1];
                float v10 = acc[nb][2] + biasS[o0];
                float v11 = acc[nb][3] + biasS[o1];
                if (mode == 0) {
                    outp[i00] = fmaxf(v00, 0.f);
                    outp[i01] = fmaxf(v01, 0.f);
                    outp[i10] = fmaxf(v10, 0.f);
                    outp[i11] = fmaxf(v11, 0.f);
                } else {
                    outp[i00] = v00 + resid[i00];
                    outp[i01] = v01 + resid[i01];
                    outp[i10] = v10 + resid[i10];
                    outp[i11] = v11 + resid[i11];
                }
            }
        }
        __syncthreads();
    }
}

// ---------------------------------------------------------------------------
extern "C" void kernel_launch(void* const* d_in, const int* in_sizes, int n_in,
                              void* d_out, int out_size)
{
    const float* x     = (const float*)d_in[0];
    const float* woff1 = (const float*)d_in[1];
    const float* boff1 = (const float*)d_in[2];
    const float* W1    = (const float*)d_in[3];
    const float* b1    = (const float*)d_in[4];
    const float* woff2 = (const float*)d_in[5];
    const float* boff2 = (const float*)d_in[6];
    const float* W2    = (const float*)d_in[7];
    const float* b2    = (const float*)d_in[8];
    const int*   lo    = (const int*)d_in[10];
    const int*   hi    = (const int*)d_in[11];
    float* out = (float*)d_out;

    float *y1, *rfh, *rfw;
    cudaGetSymbolAddress((void**)&y1,  g_y1);
    cudaGetSymbolAddress((void**)&rfh, g_rfh);
    cudaGetSymbolAddress((void**)&rfw, g_rfw);

    cudaFuncSetAttribute(arconv_mma, cudaFuncAttributeMaxDynamicSharedMemorySize, SMEM_TOTAL);

    // Layer 1
    offset_conv<<<NP / 256, 256>>>(x, woff1, boff1, lo, hi, rfh, rfw);
    arconv_mma<<<128, 512, SMEM_TOTAL>>>(x, rfh, rfw, W1, b1, nullptr, y1, 0);

    // Layer 2 (+ residual)
    offset_conv<<<NP / 256, 256>>>(y1, woff2, boff2, lo, hi, rfh, rfw);
    arconv_mma<<<128, 512, SMEM_TOTAL>>>(y1, rfh, rfw, W2, b2, x, out, 1);
}